// round 5
// baseline (speedup 1.0000x reference)
#include <cuda_runtime.h>
#include <cstdint>

#define B_  256
#define L_  128
#define H_  256
#define H4_ 1024
#define BH_ (B_*H_)
#define BL_ (B_*L_)

__device__ float g_buf[51412992];
__device__ int   g_pos0;

__device__ __forceinline__ float xla_tanh(float x) {
    float ax = fabsf(x);
    float cx = fminf(fmaxf(x, -7.90531110763549805f), 7.90531110763549805f);
    float x2 = cx * cx;
    float p = -2.76076847742355e-16f;
    p = fmaf(p, x2,  2.00018790482477e-13f);
    p = fmaf(p, x2, -8.60467152213735e-11f);
    p = fmaf(p, x2,  5.12229709037114e-08f);
    p = fmaf(p, x2,  1.48572235717979e-05f);
    p = fmaf(p, x2,  6.37261928875436e-04f);
    p = fmaf(p, x2,  4.89352455891786e-03f);
    p = cx * p;
    float q = 1.19825839466702e-06f;
    q = fmaf(q, x2, 1.18534705686654e-04f);
    q = fmaf(q, x2, 2.26843463243900e-03f);
    q = fmaf(q, x2, 4.89352518554385e-03f);
    float inv; asm("rcp.approx.f32 %0, %1;" : "=f"(inv) : "f"(q));
    inv = inv * (2.0f - q * inv);
    float r = p * inv;
    return (ax < 0.0004f) ? x : r;
}
__device__ __forceinline__ float sigmoidx(float x) {
    return fmaf(0.5f, xla_tanh(0.5f * x), 0.5f);
}
__device__ __forceinline__ float wredsum(float v) {
    #pragma unroll
    for (int o = 16; o; o >>= 1) v += __shfl_xor_sync(0xffffffffu, v, o);
    return v;
}

// C[M,N] = A[M,K] @ op(W) (+bias). WT: W is [N,K] -> A@W^T. else W is [K,N] -> A@W.
template<int BM, bool WT>
__global__ __launch_bounds__(256) void gemm_k(
    const float* __restrict__ A, const float* __restrict__ W,
    const float* __restrict__ bias, float* __restrict__ C, int N, int K)
{
    const int BN = 64, KC = 32, MR = BM / 16;
    __shared__ float As[BM][KC + 1];
    __shared__ float Ws[KC][BN + 4];
    int tid = threadIdx.x, tx = tid & 15, ty = tid >> 4;
    int m0 = blockIdx.y * BM, n0 = blockIdx.x * BN;
    float acc[MR][4];
    #pragma unroll
    for (int i = 0; i < MR; i++) { acc[i][0]=0.f; acc[i][1]=0.f; acc[i][2]=0.f; acc[i][3]=0.f; }

    for (int kc = 0; kc < K; kc += KC) {
        __syncthreads();
        #pragma unroll
        for (int i = 0; i < (BM * KC) / 256; i++) {
            int idx = tid + i * 256, k = idx & 31, m = idx >> 5;
            As[m][k] = A[(size_t)(m0 + m) * K + kc + k];
        }
        #pragma unroll
        for (int i = 0; i < (KC * BN) / 256; i++) {
            int idx = tid + i * 256;
            if (WT) { int k = idx & 31, n = idx >> 5; Ws[k][n] = W[(size_t)(n0 + n) * K + kc + k]; }
            else    { int n = idx & 63, k = idx >> 6; Ws[k][n] = W[(size_t)(kc + k) * N + n0 + n]; }
        }
        __syncthreads();
        #pragma unroll
        for (int k = 0; k < KC; k++) {
            float b0 = Ws[k][tx*4+0], b1 = Ws[k][tx*4+1], b2 = Ws[k][tx*4+2], b3 = Ws[k][tx*4+3];
            #pragma unroll
            for (int i = 0; i < MR; i++) {
                float a = As[ty*MR + i][k];
                acc[i][0] = fmaf(a, b0, acc[i][0]);
                acc[i][1] = fmaf(a, b1, acc[i][1]);
                acc[i][2] = fmaf(a, b2, acc[i][2]);
                acc[i][3] = fmaf(a, b3, acc[i][3]);
            }
        }
    }
    #pragma unroll
    for (int i = 0; i < MR; i++) {
        int m = m0 + ty * MR + i;
        #pragma unroll
        for (int j = 0; j < 4; j++) {
            int n = n0 + tx * 4 + j;
            float v2 = acc[i][j];
            if (bias) v2 += bias[n];
            C[(size_t)m * N + n] = v2;
        }
    }
}

__global__ void init_kernel(const float* __restrict__ enc, const float* __restrict__ fs,
                            float* c0, float* h0, float* cst0, float* mask)
{
    int b = blockIdx.x, n = threadIdx.x;
    const float* p = enc + (size_t)b * L_ * H_ + n;
    float s = 0.f;
    for (int l = 0; l < L_; l++) s += p[(size_t)l * H_];
    c0[b*H_ + n] = s;
    cst0[b*H_ + n] = s;
    h0[b*H_ + n] = fs[n];
    if (n < L_) mask[b*L_ + n] = 0.f;
    if (b == 0 && n == 0) g_pos0 = 0;
}

__global__ void lstm_act_kernel(const float* __restrict__ gates,
    const float* __restrict__ xwpre, const float* __restrict__ xw0,
    const float* __restrict__ bih, const float* __restrict__ bhh,
    const float* __restrict__ enc, const float* __restrict__ c0,
    const float* __restrict__ hcur, const float* __restrict__ ccur,
    float* __restrict__ hnew, float* __restrict__ cnew, int t,
    float* __restrict__ o_s0, float* __restrict__ o_s1, float* __restrict__ o_il)
{
    int b = blockIdx.x, n = threadIdx.x;
    int p = g_pos0;
    const float* xw = (t == 0) ? (xw0 + (size_t)b * H4_) : (xwpre + ((size_t)b * L_ + p) * H4_);
    const float* gb = gates + (size_t)b * H4_;
    float gi = gb[n]        + xw[n]        + bih[n]        + bhh[n];
    float gf = gb[H_ + n]   + xw[H_ + n]   + bih[H_ + n]   + bhh[H_ + n];
    float gg = gb[2*H_ + n] + xw[2*H_ + n] + bih[2*H_ + n] + bhh[2*H_ + n];
    float go = gb[3*H_ + n] + xw[3*H_ + n] + bih[3*H_ + n] + bhh[3*H_ + n];
    float c = ccur[b*H_ + n], h = hcur[b*H_ + n];
    float c2 = sigmoidx(gf) * c + sigmoidx(gi) * xla_tanh(gg);
    float h2 = sigmoidx(go) * xla_tanh(c2);
    hnew[b*H_ + n] = h2; cnew[b*H_ + n] = c2;
    size_t ob = ((size_t)b * L_ + t) * H_ + n;
    o_s0[ob] = h; o_s1[ob] = c;
    o_il[ob] = (t == 0) ? c0[b*H_ + n] : enc[((size_t)b * L_ + p) * H_ + n];
}

__global__ void glimpse_kernel(const float* __restrict__ encg, const float* __restrict__ qg,
    const float* __restrict__ vg, const float* __restrict__ mask,
    const float* __restrict__ enc, const float* __restrict__ h2v, float* __restrict__ gl)
{
    int b = blockIdx.x, tid = threadIdx.x, lane = tid & 31, w = tid >> 5;
    __shared__ float q_sm[H_], v_sm[H_], sc[L_], red[8];
    q_sm[tid] = qg[b*H_ + tid]; v_sm[tid] = vg[tid];
    __syncthreads();
    for (int li = 0; li < 16; li++) {
        int l = w * 16 + li;
        const float* row = encg + ((size_t)b * L_ + l) * H_;
        float acc = 0.f;
        #pragma unroll
        for (int h0 = 0; h0 < H_; h0 += 32)
            acc = fmaf(v_sm[h0 + lane], xla_tanh(row[h0 + lane] + q_sm[h0 + lane]), acc);
        acc = wredsum(acc);
        if (lane == 0) sc[l] = acc;
    }
    __syncthreads();
    float sval = (tid < L_) ? sc[tid] - 1e8f * mask[b*L_ + tid] : -3.4e38f;
    float m = sval;
    #pragma unroll
    for (int o = 16; o; o >>= 1) m = fmaxf(m, __shfl_xor_sync(0xffffffffu, m, o));
    if (lane == 0) red[w] = m;
    __syncthreads();
    if (tid == 0) { float mm = red[0]; for (int i = 1; i < 8; i++) mm = fmaxf(mm, red[i]); red[0] = mm; }
    __syncthreads();
    float mx = red[0];
    float e = (tid < L_) ? expf(sval - mx) : 0.f;
    float s = wredsum(e);
    __syncthreads();
    if (lane == 0) red[w] = s;
    __syncthreads();
    if (tid == 0) { float ss = red[0]; for (int i = 1; i < 8; i++) ss += red[i]; red[0] = ss; }
    __syncthreads();
    float denom = red[0];
    if (tid < L_) sc[tid] = e / denom;
    __syncthreads();
    float acc = 0.f;
    const float* ebase = enc + (size_t)b * L_ * H_ + tid;
    #pragma unroll 8
    for (int l = 0; l < L_; l++) acc = fmaf(sc[l], ebase[(size_t)l * H_], acc);
    gl[b*H_ + tid] = acc + h2v[b*H_ + tid];
}

__global__ void point_kernel(const float* __restrict__ encp, const float* __restrict__ qp,
    const float* __restrict__ vv, float* __restrict__ mask,
    const float* __restrict__ u1, const float* __restrict__ u2, int t,
    float* __restrict__ o_pos, float* __restrict__ o_ms)
{
    int b = blockIdx.x, tid = threadIdx.x, lane = tid & 31, w = tid >> 5;
    __shared__ float q_sm[H_], v_sm[H_], sc[L_];
    __shared__ float redv[8]; __shared__ int redi[8];
    q_sm[tid] = qp[b*H_ + tid]; v_sm[tid] = vv[tid];
    __syncthreads();
    for (int li = 0; li < 16; li++) {
        int l = w * 16 + li;
        const float* row = encp + ((size_t)b * L_ + l) * H_;
        float acc = 0.f;
        #pragma unroll
        for (int h0 = 0; h0 < H_; h0 += 32)
            acc = fmaf(v_sm[h0 + lane], xla_tanh(row[h0 + lane] + q_sm[h0 + lane]), acc);
        acc = wredsum(acc);
        if (lane == 0) sc[l] = acc;
    }
    __syncthreads();
    float y = -3.4e38f; int idx = 0x7fffffff;
    if (tid < L_) {
        float masked = sc[tid] - 1e7f * mask[b*L_ + tid];
        o_ms[((size_t)b * L_ + t) * L_ + tid] = masked;
        float g1 = -logf(-logf(u1[((size_t)t * B_ + b) * L_ + tid]));
        float g2 = -logf(-logf(u2[((size_t)t * B_ + b) * L_ + tid]));
        y = (masked + g1) / 3.0f + g2;
        idx = tid;
    }
    #pragma unroll
    for (int o = 16; o; o >>= 1) {
        float oy = __shfl_xor_sync(0xffffffffu, y, o);
        int   oi = __shfl_xor_sync(0xffffffffu, idx, o);
        if (oy > y || (oy == y && oi < idx)) { y = oy; idx = oi; }
    }
    if (lane == 0) { redv[w] = y; redi[w] = idx; }
    __syncthreads();
    if (tid == 0) {
        float by = redv[0]; int bi = redi[0];
        for (int i = 1; i < 8; i++)
            if (redv[i] > by || (redv[i] == by && redi[i] < bi)) { by = redv[i]; bi = redi[i]; }
        o_pos[(size_t)b * L_ + t] = (float)bi;
        mask[b*L_ + bi] += 1.0f;
        if (b == 0) g_pos0 = bi;
    }
}

extern "C" void kernel_launch(void* const* d_in, const int* in_sizes, int n_in,
                              void* d_out, int out_size)
{
    float* base = nullptr;
    if (cudaGetSymbolAddress((void**)&base, g_buf) != cudaSuccess || base == nullptr)
        return;

    const float* enc  = (const float*)d_in[0];
    const float* fs   = (const float*)d_in[1];
    const float* Wrgw = (const float*)d_in[2];
    const float* Wrgb = (const float*)d_in[3];
    const float* Wqg  = (const float*)d_in[4];
    const float* vg   = (const float*)d_in[5];
    const float* Wrw  = (const float*)d_in[6];
    const float* Wrb  = (const float*)d_in[7];
    const float* Wq   = (const float*)d_in[8];
    const float* vv   = (const float*)d_in[9];
    const float* Wih  = (const float*)d_in[10];
    const float* Whh  = (const float*)d_in[11];
    const float* bih  = (const float*)d_in[12];
    const float* bhh  = (const float*)d_in[13];
    const float* u1   = (const float*)d_in[14];
    const float* u2   = (const float*)d_in[15];

    float* out   = (float*)d_out;
    float* o_pos = out;                                   // (B, L)
    float* o_ms  = o_pos + (size_t)B_ * L_;               // (B, L, L)
    float* o_s0  = o_ms  + (size_t)B_ * L_ * L_;          // (B, L, H)
    float* o_s1  = o_s0  + (size_t)B_ * L_ * H_;          // (B, L, H)
    float* o_il  = o_s1  + (size_t)B_ * L_ * H_;          // (B, L, H)

    float* s_encg = base;
    float* s_enc  = s_encg + (size_t)BL_ * H_;
    float* s_xwp  = s_enc  + (size_t)BL_ * H_;
    float* s_xw0  = s_xwp  + (size_t)BL_ * H4_;
    float* s_c0   = s_xw0  + (size_t)B_ * H4_;
    float* s_h    = s_c0   + BH_;
    float* s_c    = s_h    + 2 * BH_;
    float* s_g    = s_c    + 2 * BH_;
    float* s_qg   = s_g    + (size_t)B_ * H4_;
    float* s_gl   = s_qg   + BH_;
    float* s_q    = s_gl   + BH_;
    float* s_mask = s_q    + BH_;

    init_kernel<<<B_, H_>>>(enc, fs, s_c0, s_h, s_c, s_mask);
    gemm_k<64, true><<<dim3(4, 512), 256>>>(enc, Wrgw, Wrgb, s_encg, H_, H_);
    gemm_k<64, true><<<dim3(4, 512), 256>>>(enc, Wrw,  Wrb,  s_enc,  H_, H_);
    gemm_k<64, true><<<dim3(16, 512), 256>>>(enc, Wih, nullptr, s_xwp, H4_, H_);
    gemm_k<64, true><<<dim3(16, 4),  256>>>(s_c0, Wih, nullptr, s_xw0, H4_, H_);

    for (int t = 0; t < L_; t++) {
        float* hc = s_h + (t & 1) * BH_;  float* hn = s_h + ((t + 1) & 1) * BH_;
        float* cc = s_c + (t & 1) * BH_;  float* cn = s_c + ((t + 1) & 1) * BH_;
        gemm_k<32, true><<<dim3(16, 8), 256>>>(hc, Whh, nullptr, s_g, H4_, H_);
        lstm_act_kernel<<<B_, H_>>>(s_g, s_xwp, s_xw0, bih, bhh, enc, s_c0,
                                    hc, cc, hn, cn, t, o_s0, o_s1, o_il);
        gemm_k<32, false><<<dim3(4, 8), 256>>>(hn, Wqg, nullptr, s_qg, H_, H_);
        glimpse_kernel<<<B_, H_>>>(s_encg, s_qg, vg, s_mask, enc, hn, s_gl);
        gemm_k<32, false><<<dim3(4, 8), 256>>>(s_gl, Wq, nullptr, s_q, H_, H_);
        point_kernel<<<B_, H_>>>(s_enc, s_q, vv, s_mask, u1, u2, t, o_pos, o_ms);
    }
}

// round 7
// speedup vs baseline: 1.1232x; 1.1232x over previous
#include <cuda_runtime.h>
#include <cstdint>

#define B_  256
#define L_  128
#define H_  256
#define H4_ 1024
#define BH_ (B_*H_)
#define BL_ (B_*L_)

__device__ float g_buf[51412992];
__device__ int   g_pos0;

__device__ __forceinline__ float xla_tanh(float x) {
    float ax = fabsf(x);
    float cx = fminf(fmaxf(x, -7.90531110763549805f), 7.90531110763549805f);
    float x2 = cx * cx;
    float p = -2.76076847742355e-16f;
    p = fmaf(p, x2,  2.00018790482477e-13f);
    p = fmaf(p, x2, -8.60467152213735e-11f);
    p = fmaf(p, x2,  5.12229709037114e-08f);
    p = fmaf(p, x2,  1.48572235717979e-05f);
    p = fmaf(p, x2,  6.37261928875436e-04f);
    p = fmaf(p, x2,  4.89352455891786e-03f);
    p = cx * p;
    float q = 1.19825839466702e-06f;
    q = fmaf(q, x2, 1.18534705686654e-04f);
    q = fmaf(q, x2, 2.26843463243900e-03f);
    q = fmaf(q, x2, 4.89352518554385e-03f);
    float inv; asm("rcp.approx.f32 %0, %1;" : "=f"(inv) : "f"(q));
    inv = inv * (2.0f - q * inv);
    float r = p * inv;
    return (ax < 0.0004f) ? x : r;
}
__device__ __forceinline__ float sigmoidx(float x) {
    return fmaf(0.5f, xla_tanh(0.5f * x), 0.5f);
}
__device__ __forceinline__ float wredsum(float v) {
    #pragma unroll
    for (int o = 16; o; o >>= 1) v += __shfl_xor_sync(0xffffffffu, v, o);
    return v;
}

// C[M,N] = A[M,K] @ W^T (+bias), W stored [N,K].
template<int BM>
__global__ __launch_bounds__(256) void gemm_k(
    const float* __restrict__ A, const float* __restrict__ W,
    const float* __restrict__ bias, float* __restrict__ C, int N, int K)
{
    const int BN = 64, KC = 32, MR = BM / 16;
    __shared__ float As[BM][KC + 1];
    __shared__ float Ws[KC][BN + 4];
    int tid = threadIdx.x, tx = tid & 15, ty = tid >> 4;
    int m0 = blockIdx.y * BM, n0 = blockIdx.x * BN;
    float acc[MR][4];
    #pragma unroll
    for (int i = 0; i < MR; i++) { acc[i][0]=0.f; acc[i][1]=0.f; acc[i][2]=0.f; acc[i][3]=0.f; }

    for (int kc = 0; kc < K; kc += KC) {
        __syncthreads();
        #pragma unroll
        for (int i = 0; i < (BM * KC) / 256; i++) {
            int idx = tid + i * 256, k = idx & 31, m = idx >> 5;
            As[m][k] = A[(size_t)(m0 + m) * K + kc + k];
        }
        #pragma unroll
        for (int i = 0; i < (KC * BN) / 256; i++) {
            int idx = tid + i * 256, k = idx & 31, n = idx >> 5;
            Ws[k][n] = W[(size_t)(n0 + n) * K + kc + k];
        }
        __syncthreads();
        #pragma unroll
        for (int k = 0; k < KC; k++) {
            float b0 = Ws[k][tx*4+0], b1 = Ws[k][tx*4+1], b2 = Ws[k][tx*4+2], b3 = Ws[k][tx*4+3];
            #pragma unroll
            for (int i = 0; i < MR; i++) {
                float a = As[ty*MR + i][k];
                acc[i][0] = fmaf(a, b0, acc[i][0]);
                acc[i][1] = fmaf(a, b1, acc[i][1]);
                acc[i][2] = fmaf(a, b2, acc[i][2]);
                acc[i][3] = fmaf(a, b3, acc[i][3]);
            }
        }
    }
    #pragma unroll
    for (int i = 0; i < MR; i++) {
        int m = m0 + ty * MR + i;
        #pragma unroll
        for (int j = 0; j < 4; j++) {
            int n = n0 + tx * 4 + j;
            float v2 = acc[i][j];
            if (bias) v2 += bias[n];
            C[(size_t)m * N + n] = v2;
        }
    }
}

__global__ void init_kernel(const float* __restrict__ enc, const float* __restrict__ fs,
                            float* c0, float* h0, float* cst0, float* mask)
{
    int b = blockIdx.x, n = threadIdx.x;
    const float* p = enc + (size_t)b * L_ * H_ + n;
    float s = 0.f;
    for (int l = 0; l < L_; l++) s += p[(size_t)l * H_];
    c0[b*H_ + n] = s;
    cst0[b*H_ + n] = s;
    h0[b*H_ + n] = fs[n];
    if (n < L_) mask[b*L_ + n] = 0.f;
    if (b == 0 && n == 0) g_pos0 = 0;
}

// ---- fused per-step kernel: LSTM act + qg GEMV + glimpse + q GEMV + pointer/Gumbel ----
__global__ __launch_bounds__(256) void fused_step_kernel(
    const float* __restrict__ gates,
    const float* __restrict__ xwpre, const float* __restrict__ xw0,
    const float* __restrict__ bih, const float* __restrict__ bhh,
    const float* __restrict__ enc, const float* __restrict__ c0,
    const float* __restrict__ hcur, const float* __restrict__ ccur,
    float* __restrict__ hnew, float* __restrict__ cnew,
    const float* __restrict__ encg, const float* __restrict__ encp,
    const float* __restrict__ Wqg, const float* __restrict__ Wq,
    const float* __restrict__ vg, const float* __restrict__ vv,
    float* __restrict__ mask,
    const float* __restrict__ u1, const float* __restrict__ u2, int t,
    float* __restrict__ o_s0, float* __restrict__ o_s1, float* __restrict__ o_il,
    float* __restrict__ o_pos, float* __restrict__ o_ms)
{
    int b = blockIdx.x, tid = threadIdx.x, lane = tid & 31, w = tid >> 5;
    __shared__ float h2_sm[H_], gl_sm[H_], q_sm[H_], vsm[H_], sc[L_];
    __shared__ float redv[8]; __shared__ int redi[8];

    // ---- phase 0: LSTM elementwise ----
    int p = g_pos0;
    {
        int n = tid;
        const float* xw = (t == 0) ? (xw0 + (size_t)b * H4_) : (xwpre + ((size_t)b * L_ + p) * H4_);
        const float* gb = gates + (size_t)b * H4_;
        float gi = gb[n]        + xw[n]        + bih[n]        + bhh[n];
        float gf = gb[H_ + n]   + xw[H_ + n]   + bih[H_ + n]   + bhh[H_ + n];
        float gg = gb[2*H_ + n] + xw[2*H_ + n] + bih[2*H_ + n] + bhh[2*H_ + n];
        float go = gb[3*H_ + n] + xw[3*H_ + n] + bih[3*H_ + n] + bhh[3*H_ + n];
        float c = ccur[b*H_ + n], h = hcur[b*H_ + n];
        float c2 = sigmoidx(gf) * c + sigmoidx(gi) * xla_tanh(gg);
        float h2 = sigmoidx(go) * xla_tanh(c2);
        hnew[b*H_ + n] = h2; cnew[b*H_ + n] = c2;
        h2_sm[n] = h2;
        vsm[n] = vg[n];
        size_t ob = ((size_t)b * L_ + t) * H_ + n;
        o_s0[ob] = h; o_s1[ob] = c;
        o_il[ob] = (t == 0) ? c0[b*H_ + n] : enc[((size_t)b * L_ + p) * H_ + n];
    }
    __syncthreads();

    // ---- phase 1: q_g = h2 @ W_q_g ----
    {
        int n = tid;
        float acc = 0.f;
        #pragma unroll 8
        for (int k = 0; k < H_; k++) acc = fmaf(h2_sm[k], Wqg[(size_t)k * H_ + n], acc);
        q_sm[n] = acc;
    }
    __syncthreads();

    // ---- phase 2: glimpse scoring ----
    for (int li = 0; li < 16; li++) {
        int l = w * 16 + li;
        const float* row = encg + ((size_t)b * L_ + l) * H_;
        float acc = 0.f;
        #pragma unroll
        for (int h0 = 0; h0 < H_; h0 += 32)
            acc = fmaf(vsm[h0 + lane], xla_tanh(row[h0 + lane] + q_sm[h0 + lane]), acc);
        acc = wredsum(acc);
        if (lane == 0) sc[l] = acc;
    }
    __syncthreads();

    // ---- softmax over sc with 1e8 mask ----
    float sval = (tid < L_) ? sc[tid] - 1e8f * mask[b*L_ + tid] : -3.4e38f;
    float m = sval;
    #pragma unroll
    for (int o = 16; o; o >>= 1) m = fmaxf(m, __shfl_xor_sync(0xffffffffu, m, o));
    if (lane == 0) redv[w] = m;
    __syncthreads();
    if (tid == 0) { float mm = redv[0]; for (int i = 1; i < 8; i++) mm = fmaxf(mm, redv[i]); redv[0] = mm; }
    __syncthreads();
    float mx = redv[0];
    __syncthreads();   // all warps have read mx before redv is overwritten below
    float e = (tid < L_) ? expf(sval - mx) : 0.f;
    float s = wredsum(e);
    if (lane == 0) redv[w] = s;
    __syncthreads();
    if (tid == 0) { float ss = redv[0]; for (int i = 1; i < 8; i++) ss += redv[i]; redv[0] = ss; }
    __syncthreads();
    float denom = redv[0];
    if (tid < L_) sc[tid] = e / denom;
    __syncthreads();

    // ---- phase 3: glimpse vector + reload vsm with v ----
    {
        int n = tid;
        float acc = 0.f;
        const float* ebase = enc + (size_t)b * L_ * H_ + n;
        #pragma unroll 8
        for (int l = 0; l < L_; l++) acc = fmaf(sc[l], ebase[(size_t)l * H_], acc);
        gl_sm[n] = acc + h2_sm[n];
        vsm[n] = vv[n];
    }
    __syncthreads();

    // ---- phase 4: q = glimpse @ W_q ----
    {
        int n = tid;
        float acc = 0.f;
        #pragma unroll 8
        for (int k = 0; k < H_; k++) acc = fmaf(gl_sm[k], Wq[(size_t)k * H_ + n], acc);
        q_sm[n] = acc;
    }
    __syncthreads();

    // ---- phase 5: pointer scoring ----
    for (int li = 0; li < 16; li++) {
        int l = w * 16 + li;
        const float* row = encp + ((size_t)b * L_ + l) * H_;
        float acc = 0.f;
        #pragma unroll
        for (int h0 = 0; h0 < H_; h0 += 32)
            acc = fmaf(vsm[h0 + lane], xla_tanh(row[h0 + lane] + q_sm[h0 + lane]), acc);
        acc = wredsum(acc);
        if (lane == 0) sc[l] = acc;
    }
    __syncthreads();

    // ---- Gumbel argmax + outputs + mask update ----
    float y = -3.4e38f; int idx = 0x7fffffff;
    if (tid < L_) {
        float masked = sc[tid] - 1e7f * mask[b*L_ + tid];
        o_ms[((size_t)b * L_ + t) * L_ + tid] = masked;
        float g1 = -logf(-logf(u1[((size_t)t * B_ + b) * L_ + tid]));
        float g2 = -logf(-logf(u2[((size_t)t * B_ + b) * L_ + tid]));
        y = (masked + g1) / 3.0f + g2;
        idx = tid;
    }
    #pragma unroll
    for (int o = 16; o; o >>= 1) {
        float oy = __shfl_xor_sync(0xffffffffu, y, o);
        int   oi = __shfl_xor_sync(0xffffffffu, idx, o);
        if (oy > y || (oy == y && oi < idx)) { y = oy; idx = oi; }
    }
    if (lane == 0) { redv[w] = y; redi[w] = idx; }
    __syncthreads();
    if (tid == 0) {
        float by = redv[0]; int bi = redi[0];
        for (int i = 1; i < 8; i++)
            if (redv[i] > by || (redv[i] == by && redi[i] < bi)) { by = redv[i]; bi = redi[i]; }
        o_pos[(size_t)b * L_ + t] = (float)bi;
        mask[b*L_ + bi] += 1.0f;
        if (b == 0) g_pos0 = bi;
    }
}

extern "C" void kernel_launch(void* const* d_in, const int* in_sizes, int n_in,
                              void* d_out, int out_size)
{
    float* base = nullptr;
    if (cudaGetSymbolAddress((void**)&base, g_buf) != cudaSuccess || base == nullptr)
        return;

    const float* enc  = (const float*)d_in[0];
    const float* fs   = (const float*)d_in[1];
    const float* Wrgw = (const float*)d_in[2];
    const float* Wrgb = (const float*)d_in[3];
    const float* Wqg  = (const float*)d_in[4];
    const float* vg   = (const float*)d_in[5];
    const float* Wrw  = (const float*)d_in[6];
    const float* Wrb  = (const float*)d_in[7];
    const float* Wq   = (const float*)d_in[8];
    const float* vv   = (const float*)d_in[9];
    const float* Wih  = (const float*)d_in[10];
    const float* Whh  = (const float*)d_in[11];
    const float* bih  = (const float*)d_in[12];
    const float* bhh  = (const float*)d_in[13];
    const float* u1   = (const float*)d_in[14];
    const float* u2   = (const float*)d_in[15];

    float* out   = (float*)d_out;
    float* o_pos = out;
    float* o_ms  = o_pos + (size_t)B_ * L_;
    float* o_s0  = o_ms  + (size_t)B_ * L_ * L_;
    float* o_s1  = o_s0  + (size_t)B_ * L_ * H_;
    float* o_il  = o_s1  + (size_t)B_ * L_ * H_;

    float* s_encg = base;
    float* s_enc  = s_encg + (size_t)BL_ * H_;
    float* s_xwp  = s_enc  + (size_t)BL_ * H_;
    float* s_xw0  = s_xwp  + (size_t)BL_ * H4_;
    float* s_c0   = s_xw0  + (size_t)B_ * H4_;
    float* s_h    = s_c0   + BH_;
    float* s_c    = s_h    + 2 * BH_;
    float* s_g    = s_c    + 2 * BH_;
    float* s_mask = s_g    + (size_t)B_ * H4_;

    init_kernel<<<B_, H_>>>(enc, fs, s_c0, s_h, s_c, s_mask);
    gemm_k<64><<<dim3(4, 512), 256>>>(enc, Wrgw, Wrgb, s_encg, H_, H_);
    gemm_k<64><<<dim3(4, 512), 256>>>(enc, Wrw,  Wrb,  s_enc,  H_, H_);
    gemm_k<64><<<dim3(16, 512), 256>>>(enc, Wih, nullptr, s_xwp, H4_, H_);
    gemm_k<64><<<dim3(16, 4),  256>>>(s_c0, Wih, nullptr, s_xw0, H4_, H_);

    for (int t = 0; t < L_; t++) {
        float* hc = s_h + (t & 1) * BH_;  float* hn = s_h + ((t + 1) & 1) * BH_;
        float* cc = s_c + (t & 1) * BH_;  float* cn = s_c + ((t + 1) & 1) * BH_;
        gemm_k<32><<<dim3(16, 8), 256>>>(hc, Whh, nullptr, s_g, H4_, H_);
        fused_step_kernel<<<B_, 256>>>(s_g, s_xwp, s_xw0, bih, bhh, enc, s_c0,
                                       hc, cc, hn, cn,
                                       s_encg, s_enc, Wqg, Wq, vg, vv,
                                       s_mask, u1, u2, t,
                                       o_s0, o_s1, o_il, o_pos, o_ms);
    }
}

// round 8
// speedup vs baseline: 1.5937x; 1.4190x over previous
#include <cuda_runtime.h>
#include <cstdint>

#define B_  256
#define L_  128
#define H_  256
#define H4_ 1024
#define BH_ (B_*H_)
#define BL_ (B_*L_)

__device__ float g_buf[51412992];
__device__ int   g_pos0;
__device__ unsigned g_barcnt = 0;
__device__ unsigned g_bargen = 0;

__device__ __forceinline__ float xla_tanh(float x) {
    float ax = fabsf(x);
    float cx = fminf(fmaxf(x, -7.90531110763549805f), 7.90531110763549805f);
    float x2 = cx * cx;
    float p = -2.76076847742355e-16f;
    p = fmaf(p, x2,  2.00018790482477e-13f);
    p = fmaf(p, x2, -8.60467152213735e-11f);
    p = fmaf(p, x2,  5.12229709037114e-08f);
    p = fmaf(p, x2,  1.48572235717979e-05f);
    p = fmaf(p, x2,  6.37261928875436e-04f);
    p = fmaf(p, x2,  4.89352455891786e-03f);
    p = cx * p;
    float q = 1.19825839466702e-06f;
    q = fmaf(q, x2, 1.18534705686654e-04f);
    q = fmaf(q, x2, 2.26843463243900e-03f);
    q = fmaf(q, x2, 4.89352518554385e-03f);
    float inv; asm("rcp.approx.f32 %0, %1;" : "=f"(inv) : "f"(q));
    inv = inv * (2.0f - q * inv);
    float r = p * inv;
    return (ax < 0.0004f) ? x : r;
}
__device__ __forceinline__ float sigmoidx(float x) {
    return fmaf(0.5f, xla_tanh(0.5f * x), 0.5f);
}
__device__ __forceinline__ float wredsum(float v) {
    #pragma unroll
    for (int o = 16; o; o >>= 1) v += __shfl_xor_sync(0xffffffffu, v, o);
    return v;
}

// grid-wide sense-reversing barrier (all 256 blocks co-resident via launch_bounds)
__device__ __forceinline__ void grid_bar() {
    __syncthreads();
    if (threadIdx.x == 0) {
        __threadfence();
        unsigned gen = *((volatile unsigned*)&g_bargen);
        unsigned t = atomicAdd(&g_barcnt, 1u);
        if (t == gridDim.x - 1) {
            *((volatile unsigned*)&g_barcnt) = 0;
            __threadfence();
            *((volatile unsigned*)&g_bargen) = gen + 1;
        } else {
            while (*((volatile unsigned*)&g_bargen) == gen) { }
            __threadfence();
        }
    }
    __syncthreads();
}

// ---- precompute GEMM: C[M,N] = A[M,K] @ W^T (+bias), W stored [N,K] ----
template<int BM>
__global__ __launch_bounds__(256) void gemm_k(
    const float* __restrict__ A, const float* __restrict__ W,
    const float* __restrict__ bias, float* __restrict__ C, int N, int K)
{
    const int BN = 64, KC = 32, MR = BM / 16;
    __shared__ float As[BM][KC + 1];
    __shared__ float Ws[KC][BN + 4];
    int tid = threadIdx.x, tx = tid & 15, ty = tid >> 4;
    int m0 = blockIdx.y * BM, n0 = blockIdx.x * BN;
    float acc[MR][4];
    #pragma unroll
    for (int i = 0; i < MR; i++) { acc[i][0]=0.f; acc[i][1]=0.f; acc[i][2]=0.f; acc[i][3]=0.f; }
    for (int kc = 0; kc < K; kc += KC) {
        __syncthreads();
        #pragma unroll
        for (int i = 0; i < (BM * KC) / 256; i++) {
            int idx = tid + i * 256, k = idx & 31, m = idx >> 5;
            As[m][k] = A[(size_t)(m0 + m) * K + kc + k];
        }
        #pragma unroll
        for (int i = 0; i < (KC * BN) / 256; i++) {
            int idx = tid + i * 256, k = idx & 31, n = idx >> 5;
            Ws[k][n] = W[(size_t)(n0 + n) * K + kc + k];
        }
        __syncthreads();
        #pragma unroll
        for (int k = 0; k < KC; k++) {
            float b0 = Ws[k][tx*4+0], b1 = Ws[k][tx*4+1], b2 = Ws[k][tx*4+2], b3 = Ws[k][tx*4+3];
            #pragma unroll
            for (int i = 0; i < MR; i++) {
                float a = As[ty*MR + i][k];
                acc[i][0] = fmaf(a, b0, acc[i][0]);
                acc[i][1] = fmaf(a, b1, acc[i][1]);
                acc[i][2] = fmaf(a, b2, acc[i][2]);
                acc[i][3] = fmaf(a, b3, acc[i][3]);
            }
        }
    }
    #pragma unroll
    for (int i = 0; i < MR; i++) {
        int m = m0 + ty * MR + i;
        #pragma unroll
        for (int j = 0; j < 4; j++) {
            int n = n0 + tx * 4 + j;
            float v2 = acc[i][j];
            if (bias) v2 += bias[n];
            C[(size_t)m * N + n] = v2;
        }
    }
}

__global__ void initc0_kernel(const float* __restrict__ enc, float* c0)
{
    int b = blockIdx.x, n = threadIdx.x;
    const float* p = enc + (size_t)b * L_ * H_ + n;
    float s = 0.f;
    for (int l = 0; l < L_; l++) s += p[(size_t)l * H_];
    c0[b*H_ + n] = s;
}

// ---------------- persistent decode loop ----------------
__global__ __launch_bounds__(256, 2) void decode_loop(
    const float* __restrict__ enc,  const float* __restrict__ encg, const float* __restrict__ encp,
    const float* __restrict__ xwpre, const float* __restrict__ xw0,
    const float* __restrict__ bih,  const float* __restrict__ bhh,
    const float* __restrict__ Whh,  const float* __restrict__ Wqg,  const float* __restrict__ Wq,
    const float* __restrict__ vg,   const float* __restrict__ vv,
    const float* __restrict__ fs,
    float* __restrict__ hbuf, float* __restrict__ gatesbuf,
    const float* __restrict__ u1, const float* __restrict__ u2,
    float* __restrict__ o_s0, float* __restrict__ o_s1, float* __restrict__ o_il,
    float* __restrict__ o_pos, float* __restrict__ o_ms)
{
    int bid = blockIdx.x, tid = threadIdx.x, lane = tid & 31, w = tid >> 5;
    int b = bid;

    __shared__ float As[32][33], Ws[32][33];
    __shared__ __align__(16) float h_sm[H_], c_sm[H_], q_sm[H_], gl_sm[H_];
    __shared__ __align__(16) float vg_sm[H_], vv_sm[H_];
    __shared__ __align__(16) float part[1024];
    __shared__ float bsum[H4_];
    __shared__ float mask_sm[L_], sc[L_];
    __shared__ float redv[8]; __shared__ int redi[8];

    // ---- one-time init ----
    for (int i = tid; i < H4_; i += 256) bsum[i] = bih[i] + bhh[i];
    vg_sm[tid] = vg[tid]; vv_sm[tid] = vv[tid];
    if (tid < L_) mask_sm[tid] = 0.f;
    {
        const float* p = enc + (size_t)b * L_ * H_ + tid;
        float s = 0.f;
        for (int l = 0; l < L_; l++) s += p[(size_t)l * H_];
        c_sm[tid] = s;
        float h0 = fs[tid];
        h_sm[tid] = h0;
        hbuf[b*H_ + tid] = h0;
    }
    if (bid == 0 && tid == 0) *((volatile int*)&g_pos0) = 0;
    grid_bar();

    for (int t = 0; t < L_; t++) {
        // ---- phase G: gates = hbuf @ Whh^T  (BM=BN=32, 8x32 = 256 tiles) ----
        {
            int mt = bid >> 5, nt = bid & 31;
            int m0 = mt * 32, n0 = nt * 32;
            int tx = tid & 31, ty = tid >> 5;           // tx: n, ty: 0..7
            float acc[4] = {0.f, 0.f, 0.f, 0.f};
            for (int kc = 0; kc < H_; kc += 32) {
                __syncthreads();
                {
                    int k = tid & 31, r = tid >> 5;     // r: 0..7
                    #pragma unroll
                    for (int i = 0; i < 4; i++)
                        As[r + i*8][k] = __ldcg(&hbuf[(size_t)(m0 + r + i*8) * H_ + kc + k]);
                    #pragma unroll
                    for (int i = 0; i < 4; i++)
                        Ws[k][r + i*8] = Whh[(size_t)(n0 + r + i*8) * H_ + kc + k];
                }
                __syncthreads();
                #pragma unroll
                for (int k = 0; k < 32; k++) {
                    float wv = Ws[k][tx];
                    #pragma unroll
                    for (int i = 0; i < 4; i++)
                        acc[i] = fmaf(As[ty*4 + i][k], wv, acc[i]);
                }
            }
            #pragma unroll
            for (int i = 0; i < 4; i++)
                gatesbuf[(size_t)(m0 + ty*4 + i) * H4_ + n0 + tx] = acc[i];
        }
        grid_bar();

        // ---- phase S (per-batch, block b) ----
        int p = *((volatile const int*)&g_pos0);
        {
            int n = tid;
            const float* xw = (t == 0) ? (xw0 + (size_t)b * H4_) : (xwpre + ((size_t)b * L_ + p) * H4_);
            const float* gb = gatesbuf + (size_t)b * H4_;
            float gi = __ldcg(&gb[n])        + xw[n]        + bsum[n];
            float gf = __ldcg(&gb[H_ + n])   + xw[H_ + n]   + bsum[H_ + n];
            float gg = __ldcg(&gb[2*H_ + n]) + xw[2*H_ + n] + bsum[2*H_ + n];
            float go = __ldcg(&gb[3*H_ + n]) + xw[3*H_ + n] + bsum[3*H_ + n];
            float c = c_sm[n], h = h_sm[n];
            float c2 = sigmoidx(gf) * c + sigmoidx(gi) * xla_tanh(gg);
            float h2 = sigmoidx(go) * xla_tanh(c2);
            size_t ob = ((size_t)b * L_ + t) * H_ + n;
            o_s0[ob] = h; o_s1[ob] = c;
            o_il[ob] = (t == 0) ? c : enc[((size_t)b * L_ + p) * H_ + n];
            c_sm[n] = c2;
            h_sm[n] = h2;
            hbuf[b*H_ + n] = h2;
        }
        __syncthreads();

        // ---- GEMV: q = h2 @ Wqg ----
        {
            int n4 = tid & 63, kq = tid >> 6, k0 = kq * 64;
            float4 acc = {0.f, 0.f, 0.f, 0.f};
            #pragma unroll 4
            for (int k = k0; k < k0 + 64; k++) {
                float xv = h_sm[k];
                float4 wv = ((const float4*)(Wqg + (size_t)k * H_))[n4];
                acc.x = fmaf(xv, wv.x, acc.x);
                acc.y = fmaf(xv, wv.y, acc.y);
                acc.z = fmaf(xv, wv.z, acc.z);
                acc.w = fmaf(xv, wv.w, acc.w);
            }
            ((float4*)(part + kq * 256))[n4] = acc;
            __syncthreads();
            q_sm[tid] = ((part[tid] + part[256 + tid]) + part[512 + tid]) + part[768 + tid];
            __syncthreads();
        }

        // ---- glimpse scoring ----
        for (int li = 0; li < 16; li++) {
            int l = w * 16 + li;
            const float4* row = (const float4*)(encg + ((size_t)b * L_ + l) * H_);
            float acc = 0.f;
            #pragma unroll
            for (int c4 = 0; c4 < 2; c4++) {
                int j = lane + c4 * 32;
                float4 r = row[j];
                float4 qv = ((const float4*)q_sm)[j];
                float4 v4 = ((const float4*)vg_sm)[j];
                acc = fmaf(v4.x, xla_tanh(r.x + qv.x), acc);
                acc = fmaf(v4.y, xla_tanh(r.y + qv.y), acc);
                acc = fmaf(v4.z, xla_tanh(r.z + qv.z), acc);
                acc = fmaf(v4.w, xla_tanh(r.w + qv.w), acc);
            }
            acc = wredsum(acc);
            if (lane == 0) sc[l] = acc;
        }
        __syncthreads();

        // ---- softmax (1e8 mask) ----
        float sval = (tid < L_) ? sc[tid] - 1e8f * mask_sm[tid] : -3.4e38f;
        float m = sval;
        #pragma unroll
        for (int o = 16; o; o >>= 1) m = fmaxf(m, __shfl_xor_sync(0xffffffffu, m, o));
        if (lane == 0) redv[w] = m;
        __syncthreads();
        if (tid == 0) { float mm = redv[0]; for (int i = 1; i < 8; i++) mm = fmaxf(mm, redv[i]); redv[0] = mm; }
        __syncthreads();
        float mx = redv[0];
        __syncthreads();
        float e = (tid < L_) ? expf(sval - mx) : 0.f;
        float s = wredsum(e);
        if (lane == 0) redv[w] = s;
        __syncthreads();
        if (tid == 0) { float ss = redv[0]; for (int i = 1; i < 8; i++) ss += redv[i]; redv[0] = ss; }
        __syncthreads();
        float denom = redv[0];
        if (tid < L_) sc[tid] = e / denom;
        __syncthreads();

        // ---- glimpse vector ----
        {
            int n4 = tid & 63, lq = tid >> 6;
            float4 acc = {0.f, 0.f, 0.f, 0.f};
            const float4* eb = (const float4*)(enc + (size_t)b * L_ * H_);
            #pragma unroll 4
            for (int l = lq * 32; l < lq * 32 + 32; l++) {
                float sl = sc[l];
                float4 ev = eb[(size_t)l * 64 + n4];
                acc.x = fmaf(sl, ev.x, acc.x);
                acc.y = fmaf(sl, ev.y, acc.y);
                acc.z = fmaf(sl, ev.z, acc.z);
                acc.w = fmaf(sl, ev.w, acc.w);
            }
            ((float4*)(part + lq * 256))[n4] = acc;
            __syncthreads();
            gl_sm[tid] = (((part[tid] + part[256 + tid]) + part[512 + tid]) + part[768 + tid]) + h_sm[tid];
            __syncthreads();
        }

        // ---- GEMV: q = glimpse @ Wq ----
        {
            int n4 = tid & 63, kq = tid >> 6, k0 = kq * 64;
            float4 acc = {0.f, 0.f, 0.f, 0.f};
            #pragma unroll 4
            for (int k = k0; k < k0 + 64; k++) {
                float xv = gl_sm[k];
                float4 wv = ((const float4*)(Wq + (size_t)k * H_))[n4];
                acc.x = fmaf(xv, wv.x, acc.x);
                acc.y = fmaf(xv, wv.y, acc.y);
                acc.z = fmaf(xv, wv.z, acc.z);
                acc.w = fmaf(xv, wv.w, acc.w);
            }
            ((float4*)(part + kq * 256))[n4] = acc;
            __syncthreads();
            q_sm[tid] = ((part[tid] + part[256 + tid]) + part[512 + tid]) + part[768 + tid];
            __syncthreads();
        }

        // ---- pointer scoring ----
        for (int li = 0; li < 16; li++) {
            int l = w * 16 + li;
            const float4* row = (const float4*)(encp + ((size_t)b * L_ + l) * H_);
            float acc = 0.f;
            #pragma unroll
            for (int c4 = 0; c4 < 2; c4++) {
                int j = lane + c4 * 32;
                float4 r = row[j];
                float4 qv = ((const float4*)q_sm)[j];
                float4 v4 = ((const float4*)vv_sm)[j];
                acc = fmaf(v4.x, xla_tanh(r.x + qv.x), acc);
                acc = fmaf(v4.y, xla_tanh(r.y + qv.y), acc);
                acc = fmaf(v4.z, xla_tanh(r.z + qv.z), acc);
                acc = fmaf(v4.w, xla_tanh(r.w + qv.w), acc);
            }
            acc = wredsum(acc);
            if (lane == 0) sc[l] = acc;
        }
        __syncthreads();

        // ---- Gumbel argmax + outputs + mask update ----
        float y = -3.4e38f; int idx = 0x7fffffff;
        if (tid < L_) {
            float masked = sc[tid] - 1e7f * mask_sm[tid];
            o_ms[((size_t)b * L_ + t) * L_ + tid] = masked;
            float g1 = -logf(-logf(u1[((size_t)t * B_ + b) * L_ + tid]));
            float g2 = -logf(-logf(u2[((size_t)t * B_ + b) * L_ + tid]));
            y = (masked + g1) / 3.0f + g2;
            idx = tid;
        }
        #pragma unroll
        for (int o = 16; o; o >>= 1) {
            float oy = __shfl_xor_sync(0xffffffffu, y, o);
            int   oi = __shfl_xor_sync(0xffffffffu, idx, o);
            if (oy > y || (oy == y && oi < idx)) { y = oy; idx = oi; }
        }
        if (lane == 0) { redv[w] = y; redi[w] = idx; }
        __syncthreads();
        if (tid == 0) {
            float by = redv[0]; int bi = redi[0];
            for (int i = 1; i < 8; i++)
                if (redv[i] > by || (redv[i] == by && redi[i] < bi)) { by = redv[i]; bi = redi[i]; }
            o_pos[(size_t)b * L_ + t] = (float)bi;
            mask_sm[bi] += 1.0f;
            if (b == 0) *((volatile int*)&g_pos0) = bi;
        }
        grid_bar();
    }
}

extern "C" void kernel_launch(void* const* d_in, const int* in_sizes, int n_in,
                              void* d_out, int out_size)
{
    float* base = nullptr;
    if (cudaGetSymbolAddress((void**)&base, g_buf) != cudaSuccess || base == nullptr)
        return;

    const float* enc  = (const float*)d_in[0];
    const float* fs   = (const float*)d_in[1];
    const float* Wrgw = (const float*)d_in[2];
    const float* Wrgb = (const float*)d_in[3];
    const float* Wqg  = (const float*)d_in[4];
    const float* vg   = (const float*)d_in[5];
    const float* Wrw  = (const float*)d_in[6];
    const float* Wrb  = (const float*)d_in[7];
    const float* Wq   = (const float*)d_in[8];
    const float* vv   = (const float*)d_in[9];
    const float* Wih  = (const float*)d_in[10];
    const float* Whh  = (const float*)d_in[11];
    const float* bih  = (const float*)d_in[12];
    const float* bhh  = (const float*)d_in[13];
    const float* u1   = (const float*)d_in[14];
    const float* u2   = (const float*)d_in[15];

    float* out   = (float*)d_out;
    float* o_pos = out;
    float* o_ms  = o_pos + (size_t)B_ * L_;
    float* o_s0  = o_ms  + (size_t)B_ * L_ * L_;
    float* o_s1  = o_s0  + (size_t)B_ * L_ * H_;
    float* o_il  = o_s1  + (size_t)B_ * L_ * H_;

    float* s_encg = base;
    float* s_enc  = s_encg + (size_t)BL_ * H_;
    float* s_xwp  = s_enc  + (size_t)BL_ * H_;
    float* s_xw0  = s_xwp  + (size_t)BL_ * H4_;
    float* s_c0   = s_xw0  + (size_t)B_ * H4_;
    float* s_h    = s_c0   + BH_;
    float* s_g    = s_h    + BH_;

    initc0_kernel<<<B_, H_>>>(enc, s_c0);
    gemm_k<64><<<dim3(4, 512), 256>>>(enc, Wrgw, Wrgb, s_encg, H_, H_);
    gemm_k<64><<<dim3(4, 512), 256>>>(enc, Wrw,  Wrb,  s_enc,  H_, H_);
    gemm_k<64><<<dim3(16, 512), 256>>>(enc, Wih, nullptr, s_xwp, H4_, H_);
    gemm_k<64><<<dim3(16, 4),  256>>>(s_c0, Wih, nullptr, s_xw0, H4_, H_);

    decode_loop<<<B_, 256>>>(enc, s_encg, s_enc, s_xwp, s_xw0,
                             bih, bhh, Whh, Wqg, Wq, vg, vv, fs,
                             s_h, s_g, u1, u2,
                             o_s0, o_s1, o_il, o_pos, o_ms);
}